// round 1
// baseline (speedup 1.0000x reference)
#include <cuda_runtime.h>
#include <cstddef>

#define S_LEN 4096
#define B_SZ  4
#define D_DIM 768
#define H_DIM 64

#define BM 64   // query tile
#define BN 32   // kv tile

// Scratch for q/k/v projections (static device arrays: allocation-free).
__device__ float g_q[B_SZ * S_LEN * H_DIM];
__device__ float g_k[B_SZ * S_LEN * H_DIM];
__device__ float g_v[B_SZ * S_LEN * H_DIM];

// ---------------------------------------------------------------------------
// Projection GEMM: C[64 rows][64 cols] per block.
// grid.x = (B*S)/64 = 256, grid.y = 3 (q, k, v).
// ---------------------------------------------------------------------------
__global__ __launch_bounds__(256) void proj_kernel(
    const float* __restrict__ x,
    const float* __restrict__ Wq,
    const float* __restrict__ Wk,
    const float* __restrict__ Wv)
{
    __shared__ float xs[64][65];
    __shared__ float ws[64][65];

    const float* W;
    float* out;
    if (blockIdx.y == 0)      { W = Wq; out = g_q; }
    else if (blockIdx.y == 1) { W = Wk; out = g_k; }
    else                      { W = Wv; out = g_v; }

    const int row0 = blockIdx.x * 64;
    const int tid  = threadIdx.x;
    const int tr   = tid / 16;   // 0..15 -> rows tr*4..tr*4+3
    const int tc   = tid % 16;   // 0..15 -> cols tc*4..tc*4+3

    float acc[4][4];
#pragma unroll
    for (int i = 0; i < 4; i++)
#pragma unroll
        for (int j = 0; j < 4; j++)
            acc[i][j] = 0.0f;

    for (int k0 = 0; k0 < D_DIM; k0 += 64) {
        // Load 64x64 x-tile and 64x64 W-tile (float4 gmem loads, scalar smem stores).
        for (int i = tid; i < 64 * 16; i += 256) {
            const int r  = i / 16;
            const int c4 = (i % 16) * 4;
            float4 xv = *reinterpret_cast<const float4*>(&x[(size_t)(row0 + r) * D_DIM + k0 + c4]);
            xs[r][c4 + 0] = xv.x; xs[r][c4 + 1] = xv.y;
            xs[r][c4 + 2] = xv.z; xs[r][c4 + 3] = xv.w;
            float4 wv = *reinterpret_cast<const float4*>(&W[(size_t)r * D_DIM + k0 + c4]);
            ws[r][c4 + 0] = wv.x; ws[r][c4 + 1] = wv.y;
            ws[r][c4 + 2] = wv.z; ws[r][c4 + 3] = wv.w;
        }
        __syncthreads();

#pragma unroll 8
        for (int kk = 0; kk < 64; kk++) {
            float a[4], b[4];
#pragma unroll
            for (int i = 0; i < 4; i++) a[i] = xs[tr * 4 + i][kk];
#pragma unroll
            for (int j = 0; j < 4; j++) b[j] = ws[tc * 4 + j][kk];
#pragma unroll
            for (int i = 0; i < 4; i++)
#pragma unroll
                for (int j = 0; j < 4; j++)
                    acc[i][j] += a[i] * b[j];
        }
        __syncthreads();
    }

#pragma unroll
    for (int i = 0; i < 4; i++)
#pragma unroll
        for (int j = 0; j < 4; j++)
            out[(size_t)(row0 + tr * 4 + i) * H_DIM + tc * 4 + j] = acc[i][j];
}

// ---------------------------------------------------------------------------
// Flash attention (online softmax), fp32.
// grid: (S/BM, B), block 256 threads.
// Thread t: query row r = t/4 within tile, h-slice c = t%4 (16 h's), and
// computes scores for 8 keys (c*8..c*8+7) of each BN=32 kv tile.
// ---------------------------------------------------------------------------
__global__ __launch_bounds__(256) void attn_kernel(
    const int* __restrict__ mask,
    float* __restrict__ out)
{
    __shared__ float qs[BM][68];
    __shared__ float ks[BN][68];
    __shared__ float vs[BN][68];
    __shared__ float ps[BM][BN + 1];
    __shared__ int   msk[BN];

    const int b     = blockIdx.y;
    const int qt    = (gridDim.x - 1) - blockIdx.x;   // big tiles first (balance)
    const int qbase = qt * BM;
    const int tid   = threadIdx.x;
    const int r     = tid >> 2;
    const int c     = tid & 3;

    const float* qptr = g_q + (size_t)b * S_LEN * H_DIM;
    const float* kptr = g_k + (size_t)b * S_LEN * H_DIM;
    const float* vptr = g_v + (size_t)b * S_LEN * H_DIM;

    // Load q tile (64 x 64).
    for (int i = tid; i < BM * 16; i += 256) {
        const int rr = i / 16;
        const int c4 = (i % 16) * 4;
        *reinterpret_cast<float4*>(&qs[rr][c4]) =
            *reinterpret_cast<const float4*>(&qptr[(size_t)(qbase + rr) * H_DIM + c4]);
    }

    float m = -1e30f;
    float l = 0.0f;
    float o[16];
#pragma unroll
    for (int i = 0; i < 16; i++) o[i] = 0.0f;

    const int   ntiles = (qbase + BM) / BN;   // causal: kv tiles 0..(qt+1)*2-1
    const float scale  = 0.125f;              // 1/sqrt(64)

    for (int kt = 0; kt < ntiles; kt++) {
        const int kbase = kt * BN;

        // Load K/V tile (32 x 64 each) + padding mask.
        for (int i = tid; i < BN * 16; i += 256) {
            const int rr = i / 16;
            const int c4 = (i % 16) * 4;
            *reinterpret_cast<float4*>(&ks[rr][c4]) =
                *reinterpret_cast<const float4*>(&kptr[(size_t)(kbase + rr) * H_DIM + c4]);
            *reinterpret_cast<float4*>(&vs[rr][c4]) =
                *reinterpret_cast<const float4*>(&vptr[(size_t)(kbase + rr) * H_DIM + c4]);
        }
        if (tid < BN) msk[tid] = mask[(size_t)b * S_LEN + kbase + tid];
        __syncthreads();

        // Scores for 8 keys.
        float s[8];
#pragma unroll
        for (int j = 0; j < 8; j++) s[j] = 0.0f;
#pragma unroll 4
        for (int h = 0; h < H_DIM; h += 4) {
            float4 qv = *reinterpret_cast<const float4*>(&qs[r][h]);
#pragma unroll
            for (int j = 0; j < 8; j++) {
                float4 kv = *reinterpret_cast<const float4*>(&ks[c * 8 + j][h]);
                s[j] += qv.x * kv.x;
                s[j] += qv.y * kv.y;
                s[j] += qv.z * kv.z;
                s[j] += qv.w * kv.w;
            }
        }

        // Mask (causal + padding) and per-row tile max.
        float mt = -1e30f;
#pragma unroll
        for (int j = 0; j < 8; j++) {
            const int key = kbase + c * 8 + j;
            const bool keep = (key <= qbase + r) && (msk[c * 8 + j] != 0);
            s[j] = keep ? s[j] * scale : -1e30f;
            mt = fmaxf(mt, s[j]);
        }
        mt = fmaxf(mt, __shfl_xor_sync(0xffffffffu, mt, 1));
        mt = fmaxf(mt, __shfl_xor_sync(0xffffffffu, mt, 2));

        const float mnew = fmaxf(m, mt);
        const float corr = __expf(m - mnew);
        const float fsc  = __expf(mt - mnew);   // 0 when tile fully masked

        float psum = 0.0f;
#pragma unroll
        for (int j = 0; j < 8; j++) {
            const float p = __expf(s[j] - mt);
            ps[r][c * 8 + j] = p;
            psum += p;
        }
        psum += __shfl_xor_sync(0xffffffffu, psum, 1);
        psum += __shfl_xor_sync(0xffffffffu, psum, 2);

        m = mnew;
        l = l * corr + fsc * psum;
#pragma unroll
        for (int i = 0; i < 16; i++) o[i] *= corr;

        __syncwarp();   // ps written/read only within warp

        // PV accumulation: o[h] += (p * fsc) * V[j][h]
#pragma unroll 8
        for (int j = 0; j < BN; j++) {
            const float p = ps[r][j] * fsc;
            const float4 v0 = *reinterpret_cast<const float4*>(&vs[j][c * 16 + 0]);
            const float4 v1 = *reinterpret_cast<const float4*>(&vs[j][c * 16 + 4]);
            const float4 v2 = *reinterpret_cast<const float4*>(&vs[j][c * 16 + 8]);
            const float4 v3 = *reinterpret_cast<const float4*>(&vs[j][c * 16 + 12]);
            o[0]  += p * v0.x; o[1]  += p * v0.y; o[2]  += p * v0.z; o[3]  += p * v0.w;
            o[4]  += p * v1.x; o[5]  += p * v1.y; o[6]  += p * v1.z; o[7]  += p * v1.w;
            o[8]  += p * v2.x; o[9]  += p * v2.y; o[10] += p * v2.z; o[11] += p * v2.w;
            o[12] += p * v3.x; o[13] += p * v3.y; o[14] += p * v3.z; o[15] += p * v3.w;
        }
        __syncthreads();
    }

    const float inv = 1.0f / l;
    float* orow = out + ((size_t)b * S_LEN + qbase + r) * H_DIM + c * 16;
#pragma unroll
    for (int i4 = 0; i4 < 4; i4++) {
        float4 w;
        w.x = o[i4 * 4 + 0] * inv;
        w.y = o[i4 * 4 + 1] * inv;
        w.z = o[i4 * 4 + 2] * inv;
        w.w = o[i4 * 4 + 3] * inv;
        *reinterpret_cast<float4*>(&orow[i4 * 4]) = w;
    }
}

// ---------------------------------------------------------------------------
extern "C" void kernel_launch(void* const* d_in, const int* in_sizes, int n_in,
                              void* d_out, int out_size)
{
    const float* x    = (const float*)d_in[0];
    const int*   mask = (const int*)  d_in[1];
    const float* Wq   = (const float*)d_in[2];
    const float* Wk   = (const float*)d_in[3];
    const float* Wv   = (const float*)d_in[4];
    float*       out  = (float*)d_out;

    dim3 pgrid((B_SZ * S_LEN) / 64, 3);
    proj_kernel<<<pgrid, 256>>>(x, Wq, Wk, Wv);

    dim3 agrid(S_LEN / BM, B_SZ);
    attn_kernel<<<agrid, 256>>>(mask, out);
}

// round 2
// speedup vs baseline: 3.0801x; 3.0801x over previous
#include <cuda_runtime.h>
#include <cstddef>

#define S_LEN 4096
#define B_SZ  4
#define D_DIM 768
#define H_DIM 64

#define BM 64   // query tile
#define BN 64   // kv tile
#define LP 68   // smem row pitch (floats)

// Scratch for q/k/v projections (static device arrays: allocation-free).
__device__ float g_q[B_SZ * S_LEN * H_DIM];
__device__ float g_k[B_SZ * S_LEN * H_DIM];
__device__ float g_v[B_SZ * S_LEN * H_DIM];

// ---------------------------------------------------------------------------
// Projection GEMM: C[64 rows][64 cols] per block.
// grid.x = (B*S)/64 = 256, grid.y = 3 (q, k, v).
// ---------------------------------------------------------------------------
__global__ __launch_bounds__(256) void proj_kernel(
    const float* __restrict__ x,
    const float* __restrict__ Wq,
    const float* __restrict__ Wk,
    const float* __restrict__ Wv)
{
    __shared__ float xs[64][65];
    __shared__ float ws[64][65];

    const float* W;
    float* out;
    if (blockIdx.y == 0)      { W = Wq; out = g_q; }
    else if (blockIdx.y == 1) { W = Wk; out = g_k; }
    else                      { W = Wv; out = g_v; }

    const int row0 = blockIdx.x * 64;
    const int tid  = threadIdx.x;
    const int tr   = tid / 16;
    const int tc   = tid % 16;

    float acc[4][4];
#pragma unroll
    for (int i = 0; i < 4; i++)
#pragma unroll
        for (int j = 0; j < 4; j++)
            acc[i][j] = 0.0f;

    for (int k0 = 0; k0 < D_DIM; k0 += 64) {
        for (int i = tid; i < 64 * 16; i += 256) {
            const int r  = i / 16;
            const int c4 = (i % 16) * 4;
            float4 xv = *reinterpret_cast<const float4*>(&x[(size_t)(row0 + r) * D_DIM + k0 + c4]);
            xs[r][c4 + 0] = xv.x; xs[r][c4 + 1] = xv.y;
            xs[r][c4 + 2] = xv.z; xs[r][c4 + 3] = xv.w;
            float4 wv = *reinterpret_cast<const float4*>(&W[(size_t)r * D_DIM + k0 + c4]);
            ws[r][c4 + 0] = wv.x; ws[r][c4 + 1] = wv.y;
            ws[r][c4 + 2] = wv.z; ws[r][c4 + 3] = wv.w;
        }
        __syncthreads();

#pragma unroll 8
        for (int kk = 0; kk < 64; kk++) {
            float a[4], b[4];
#pragma unroll
            for (int i = 0; i < 4; i++) a[i] = xs[tr * 4 + i][kk];
#pragma unroll
            for (int j = 0; j < 4; j++) b[j] = ws[tc * 4 + j][kk];
#pragma unroll
            for (int i = 0; i < 4; i++)
#pragma unroll
                for (int j = 0; j < 4; j++)
                    acc[i][j] += a[i] * b[j];
        }
        __syncthreads();
    }

#pragma unroll
    for (int i = 0; i < 4; i++)
#pragma unroll
        for (int j = 0; j < 4; j++)
            out[(size_t)(row0 + tr * 4 + i) * H_DIM + tc * 4 + j] = acc[i][j];
}

// ---------------------------------------------------------------------------
// Flash attention, register-tiled 64x64 score block, fp32.
// 256 threads: thread (ti, tj), ti=tid/16 (rows ti*4..+3), tj=tid%16.
// Scores: thread computes 4 rows x 4 keys, keys = tj + 16*jj (consecutive-row
// smem access pattern -> conflict-free). PV: 4 rows x 4 h (h = tj*4..+3).
// ---------------------------------------------------------------------------
__global__ __launch_bounds__(256, 2) void attn_kernel(
    const int* __restrict__ mask,
    float* __restrict__ out)
{
    extern __shared__ float sm[];
    float* qs = sm;                 // [BM][LP]
    float* ks = qs + BM * LP;       // [BN][LP]
    float* vs = ks + BN * LP;       // [BN][LP]
    float* ps = vs + BN * LP;       // [BM][LP]
    __shared__ int msk[BN];

    const int b  = blockIdx.y;
    const int bx = blockIdx.x;
    // Complementary pairing: adjacent block ids get (k, 63-k) workloads.
    const int qt    = (bx & 1) ? (63 - (bx >> 1)) : (bx >> 1);
    const int qbase = qt * BM;
    const int tid   = threadIdx.x;
    const int ti    = tid >> 4;
    const int tj    = tid & 15;

    const float* qp = g_q + (size_t)b * S_LEN * H_DIM;
    const float* kp = g_k + (size_t)b * S_LEN * H_DIM;
    const float* vp = g_v + (size_t)b * S_LEN * H_DIM;

    // Load q tile (64 x 64).
    for (int i = tid; i < BM * 16; i += 256) {
        const int r  = i >> 4;
        const int c4 = (i & 15) * 4;
        *reinterpret_cast<float4*>(&qs[r * LP + c4]) =
            *reinterpret_cast<const float4*>(&qp[(size_t)(qbase + r) * H_DIM + c4]);
    }

    float m[4], l[4], o[4][4];
#pragma unroll
    for (int i = 0; i < 4; i++) {
        m[i] = -1e30f; l[i] = 0.0f;
#pragma unroll
        for (int j = 0; j < 4; j++) o[i][j] = 0.0f;
    }

    const int   ntiles = qt + 1;
    const float scale  = 0.125f;   // 1/sqrt(64)

    for (int kt = 0; kt < ntiles; kt++) {
        const int kbase = kt * BN;

        __syncthreads();   // prev PV done; also covers first-iter q visibility
        for (int i = tid; i < BN * 16; i += 256) {
            const int r  = i >> 4;
            const int c4 = (i & 15) * 4;
            *reinterpret_cast<float4*>(&ks[r * LP + c4]) =
                *reinterpret_cast<const float4*>(&kp[(size_t)(kbase + r) * H_DIM + c4]);
            *reinterpret_cast<float4*>(&vs[r * LP + c4]) =
                *reinterpret_cast<const float4*>(&vp[(size_t)(kbase + r) * H_DIM + c4]);
        }
        if (tid < BN) msk[tid] = mask[(size_t)b * S_LEN + kbase + tid];
        __syncthreads();

        // ---- scores: 4 rows x 4 keys (keys tj + 16*jj) ----
        float s[4][4];
#pragma unroll
        for (int i = 0; i < 4; i++)
#pragma unroll
            for (int j = 0; j < 4; j++) s[i][j] = 0.0f;

#pragma unroll 4
        for (int h = 0; h < H_DIM; h += 4) {
            float4 qv[4], kv[4];
#pragma unroll
            for (int ii = 0; ii < 4; ii++)
                qv[ii] = *reinterpret_cast<const float4*>(&qs[(ti * 4 + ii) * LP + h]);
#pragma unroll
            for (int jj = 0; jj < 4; jj++)
                kv[jj] = *reinterpret_cast<const float4*>(&ks[(tj + 16 * jj) * LP + h]);
#pragma unroll
            for (int ii = 0; ii < 4; ii++)
#pragma unroll
                for (int jj = 0; jj < 4; jj++) {
                    s[ii][jj] += qv[ii].x * kv[jj].x;
                    s[ii][jj] += qv[ii].y * kv[jj].y;
                    s[ii][jj] += qv[ii].z * kv[jj].z;
                    s[ii][jj] += qv[ii].w * kv[jj].w;
                }
        }

        // ---- mask + online softmax (row group shared by 16 lanes) ----
#pragma unroll
        for (int ii = 0; ii < 4; ii++) {
            const int row = qbase + ti * 4 + ii;
            float mt = -1e30f;
            float sv[4];
#pragma unroll
            for (int jj = 0; jj < 4; jj++) {
                const int kk  = tj + 16 * jj;
                const int key = kbase + kk;
                const bool keep = (key <= row) && (msk[kk] != 0);
                const float v = keep ? s[ii][jj] * scale : -1e30f;
                sv[jj] = v;
                mt = fmaxf(mt, v);
            }
            mt = fmaxf(mt, __shfl_xor_sync(0xffffffffu, mt, 1));
            mt = fmaxf(mt, __shfl_xor_sync(0xffffffffu, mt, 2));
            mt = fmaxf(mt, __shfl_xor_sync(0xffffffffu, mt, 4));
            mt = fmaxf(mt, __shfl_xor_sync(0xffffffffu, mt, 8));

            const float mn   = fmaxf(m[ii], mt);
            const float corr = __expf(m[ii] - mn);
            m[ii] = mn;

            float rs = 0.0f;
#pragma unroll
            for (int jj = 0; jj < 4; jj++) {
                const float p = __expf(sv[jj] - mn);
                ps[(ti * 4 + ii) * LP + tj + 16 * jj] = p;
                rs += p;
            }
            rs += __shfl_xor_sync(0xffffffffu, rs, 1);
            rs += __shfl_xor_sync(0xffffffffu, rs, 2);
            rs += __shfl_xor_sync(0xffffffffu, rs, 4);
            rs += __shfl_xor_sync(0xffffffffu, rs, 8);

            l[ii] = l[ii] * corr + rs;
#pragma unroll
            for (int c = 0; c < 4; c++) o[ii][c] *= corr;
        }
        __syncwarp();   // ps produced/consumed within the same warp row-group

        // ---- PV: o[4 rows][4 h], h = tj*4..+3 ----
#pragma unroll 4
        for (int k0 = 0; k0 < BN; k0 += 4) {
            float4 pv[4], vv[4];
#pragma unroll
            for (int ii = 0; ii < 4; ii++)
                pv[ii] = *reinterpret_cast<const float4*>(&ps[(ti * 4 + ii) * LP + k0]);
#pragma unroll
            for (int kk = 0; kk < 4; kk++)
                vv[kk] = *reinterpret_cast<const float4*>(&vs[(k0 + kk) * LP + tj * 4]);
#pragma unroll
            for (int ii = 0; ii < 4; ii++) {
                o[ii][0] += pv[ii].x * vv[0].x; o[ii][1] += pv[ii].x * vv[0].y;
                o[ii][2] += pv[ii].x * vv[0].z; o[ii][3] += pv[ii].x * vv[0].w;
                o[ii][0] += pv[ii].y * vv[1].x; o[ii][1] += pv[ii].y * vv[1].y;
                o[ii][2] += pv[ii].y * vv[1].z; o[ii][3] += pv[ii].y * vv[1].w;
                o[ii][0] += pv[ii].z * vv[2].x; o[ii][1] += pv[ii].z * vv[2].y;
                o[ii][2] += pv[ii].z * vv[2].z; o[ii][3] += pv[ii].z * vv[2].w;
                o[ii][0] += pv[ii].w * vv[3].x; o[ii][1] += pv[ii].w * vv[3].y;
                o[ii][2] += pv[ii].w * vv[3].z; o[ii][3] += pv[ii].w * vv[3].w;
            }
        }
    }

    // ---- epilogue ----
#pragma unroll
    for (int ii = 0; ii < 4; ii++) {
        const float inv = 1.0f / l[ii];
        float4 w;
        w.x = o[ii][0] * inv; w.y = o[ii][1] * inv;
        w.z = o[ii][2] * inv; w.w = o[ii][3] * inv;
        *reinterpret_cast<float4*>(
            &out[((size_t)b * S_LEN + qbase + ti * 4 + ii) * H_DIM + tj * 4]) = w;
    }
}

// ---------------------------------------------------------------------------
extern "C" void kernel_launch(void* const* d_in, const int* in_sizes, int n_in,
                              void* d_out, int out_size)
{
    const float* x    = (const float*)d_in[0];
    const int*   mask = (const int*)  d_in[1];
    const float* Wq   = (const float*)d_in[2];
    const float* Wk   = (const float*)d_in[3];
    const float* Wv   = (const float*)d_in[4];
    float*       out  = (float*)d_out;

    dim3 pgrid((B_SZ * S_LEN) / 64, 3);
    proj_kernel<<<pgrid, 256>>>(x, Wq, Wk, Wv);

    const int smem_bytes = (BM + 2 * BN + BM) * LP * sizeof(float);  // 69632
    cudaFuncSetAttribute(attn_kernel, cudaFuncAttributeMaxDynamicSharedMemorySize,
                         smem_bytes);
    dim3 agrid(S_LEN / BM, B_SZ);
    attn_kernel<<<agrid, 256, smem_bytes>>>(mask, out);
}

// round 4
// speedup vs baseline: 5.0073x; 1.6257x over previous
#include <cuda_runtime.h>
#include <cstdint>
#include <cstddef>

#define S_LEN 4096
#define B_SZ  4
#define D_DIM 768
#define H_DIM 64

#define BM 128   // attention query-tile rows
#define BN 64    // attention kv-tile
#define PIT 68   // smem pitch in words (bank = 4*row + col: conflict-free frags)

// Scratch for q/k/v projections (static device arrays: allocation-free).
__device__ float g_q[B_SZ * S_LEN * H_DIM];
__device__ float g_k[B_SZ * S_LEN * H_DIM];
__device__ float g_v[B_SZ * S_LEN * H_DIM];

// ===========================================================================
// tf32 helpers (sm_80+ PTX only — no sm_103a-gated instructions)
// ===========================================================================
__device__ __forceinline__ uint32_t f2tf32(float f) {
    uint32_t r;
    asm("cvt.rna.tf32.f32 %0, %1;" : "=r"(r) : "f"(f));
    return r;
}

__device__ __forceinline__ void hilo(float v, uint32_t& h, uint32_t& l) {
    h = f2tf32(v);
    l = f2tf32(v - __uint_as_float(h));
}

// D += A(16x8) * B(8x8), tf32 inputs, f32 accumulate.
__device__ __forceinline__ void mma8(float* c, const uint32_t* a, const uint32_t* b) {
    asm volatile(
        "mma.sync.aligned.m16n8k8.row.col.f32.tf32.tf32.f32 "
        "{%0,%1,%2,%3}, {%4,%5,%6,%7}, {%8,%9}, {%0,%1,%2,%3};"
        : "+f"(c[0]), "+f"(c[1]), "+f"(c[2]), "+f"(c[3])
        : "r"(a[0]), "r"(a[1]), "r"(a[2]), "r"(a[3]), "r"(b[0]), "r"(b[1]));
}

// ---------------------------------------------------------------------------
// Projection: out[row][h] = sum_d x[row][d] * W[h][d], 3xTF32.
// 512 threads, 16 warps: warp (wr 0..7: 16 rows, wc 0..1: 32 cols).
// grid = (16384/128, 3).
// ---------------------------------------------------------------------------
__global__ __launch_bounds__(512) void proj_kernel(
    const float* __restrict__ x,
    const float* __restrict__ Wq,
    const float* __restrict__ Wk,
    const float* __restrict__ Wv)
{
    extern __shared__ uint32_t psm[];
    uint32_t* xh = psm;             // [128][PIT]
    uint32_t* xl = xh + 128 * PIT;
    uint32_t* wh = xl + 128 * PIT;  // [64][PIT]
    uint32_t* wl = wh + 64 * PIT;

    const float* W;
    float* out;
    if (blockIdx.y == 0)      { W = Wq; out = g_q; }
    else if (blockIdx.y == 1) { W = Wk; out = g_k; }
    else                      { W = Wv; out = g_v; }

    const int row0 = blockIdx.x * 128;
    const int tid  = threadIdx.x;
    const int wid  = tid >> 5, lane = tid & 31;
    const int wr   = wid & 7, wc = wid >> 3;
    const int g    = lane >> 2, tq = lane & 3;

    float acc[4][4];
#pragma unroll
    for (int i = 0; i < 4; i++)
#pragma unroll
        for (int j = 0; j < 4; j++) acc[i][j] = 0.0f;

    for (int kc = 0; kc < 12; kc++) {
        const int k0 = kc * 64;
        __syncthreads();
        for (int i = tid; i < 128 * 16; i += 512) {
            const int r = i >> 4, c4 = (i & 15) << 2;
            float4 v = *reinterpret_cast<const float4*>(&x[(size_t)(row0 + r) * D_DIM + k0 + c4]);
            uint32_t h, l;
            hilo(v.x, h, l); xh[r * PIT + c4 + 0] = h; xl[r * PIT + c4 + 0] = l;
            hilo(v.y, h, l); xh[r * PIT + c4 + 1] = h; xl[r * PIT + c4 + 1] = l;
            hilo(v.z, h, l); xh[r * PIT + c4 + 2] = h; xl[r * PIT + c4 + 2] = l;
            hilo(v.w, h, l); xh[r * PIT + c4 + 3] = h; xl[r * PIT + c4 + 3] = l;
        }
        for (int i = tid; i < 64 * 16; i += 512) {
            const int r = i >> 4, c4 = (i & 15) << 2;
            float4 v = *reinterpret_cast<const float4*>(&W[(size_t)r * D_DIM + k0 + c4]);
            uint32_t h, l;
            hilo(v.x, h, l); wh[r * PIT + c4 + 0] = h; wl[r * PIT + c4 + 0] = l;
            hilo(v.y, h, l); wh[r * PIT + c4 + 1] = h; wl[r * PIT + c4 + 1] = l;
            hilo(v.z, h, l); wh[r * PIT + c4 + 2] = h; wl[r * PIT + c4 + 2] = l;
            hilo(v.w, h, l); wh[r * PIT + c4 + 3] = h; wl[r * PIT + c4 + 3] = l;
        }
        __syncthreads();

#pragma unroll
        for (int k8 = 0; k8 < 8; k8++) {
            const int kk = k8 * 8;
            const int ar = wr * 16 + g;
            uint32_t ah[4], al[4];
            ah[0] = xh[ar * PIT + kk + tq];       ah[1] = xh[(ar + 8) * PIT + kk + tq];
            ah[2] = xh[ar * PIT + kk + tq + 4];   ah[3] = xh[(ar + 8) * PIT + kk + tq + 4];
            al[0] = xl[ar * PIT + kk + tq];       al[1] = xl[(ar + 8) * PIT + kk + tq];
            al[2] = xl[ar * PIT + kk + tq + 4];   al[3] = xl[(ar + 8) * PIT + kk + tq + 4];
#pragma unroll
            for (int ni = 0; ni < 4; ni++) {
                const int hc = wc * 32 + ni * 8 + g;
                uint32_t bh[2] = { wh[hc * PIT + kk + tq], wh[hc * PIT + kk + tq + 4] };
                uint32_t bl[2] = { wl[hc * PIT + kk + tq], wl[hc * PIT + kk + tq + 4] };
                mma8(acc[ni], ah, bh);
                mma8(acc[ni], ah, bl);
                mma8(acc[ni], al, bh);
            }
        }
    }

#pragma unroll
    for (int ni = 0; ni < 4; ni++)
#pragma unroll
        for (int ri = 0; ri < 2; ri++)
#pragma unroll
            for (int c1 = 0; c1 < 2; c1++) {
                const int row = row0 + wr * 16 + ri * 8 + g;
                const int col = wc * 32 + ni * 8 + 2 * tq + c1;
                out[(size_t)row * H_DIM + col] = acc[ni][ri * 2 + c1];
            }
}

// ---------------------------------------------------------------------------
// Flash attention via mma.sync tf32 (3x for QK^T, 2x for PV).
// 512 threads, 16 warps: warp (wr 0..7: 16 q-rows, wc 0..1: 32 cols).
// grid = (32, 4), causal-paired.
// ---------------------------------------------------------------------------
__global__ __launch_bounds__(512) void attn_mma(
    const int* __restrict__ mask,
    float* __restrict__ out)
{
    extern __shared__ uint32_t asm_[];
    uint32_t* qh = asm_;              // [128][PIT]
    uint32_t* ql = qh + 128 * PIT;
    uint32_t* kh = ql + 128 * PIT;    // [64][PIT]
    uint32_t* kl = kh + 64 * PIT;
    uint32_t* vh = kl + 64 * PIT;     // [64][PIT]
    uint32_t* vl = vh + 64 * PIT;
    uint32_t* ph = vl + 64 * PIT;     // [128][PIT]
    __shared__ float redm[BM][2];
    __shared__ float reds[BM][2];
    __shared__ int   msk[BN];

    const int tid  = threadIdx.x;
    const int wid  = tid >> 5, lane = tid & 31;
    const int wr   = wid & 7, wc = wid >> 3;
    const int g    = lane >> 2, tq = lane & 3;

    const int b  = blockIdx.y;
    const int bx = blockIdx.x;
    const int qt = (bx & 1) ? (31 - (bx >> 1)) : (bx >> 1);
    const int qbase = qt * BM;

    const float* qp = g_q + (size_t)b * S_LEN * H_DIM;
    const float* kp = g_k + (size_t)b * S_LEN * H_DIM;
    const float* vp = g_v + (size_t)b * S_LEN * H_DIM;

    // Load Q tile (128 x 64) as hi/lo tf32.
    for (int i = tid; i < BM * 16; i += 512) {
        const int r = i >> 4, c4 = (i & 15) << 2;
        float4 v = *reinterpret_cast<const float4*>(&qp[(size_t)(qbase + r) * H_DIM + c4]);
        uint32_t h, l;
        hilo(v.x, h, l); qh[r * PIT + c4 + 0] = h; ql[r * PIT + c4 + 0] = l;
        hilo(v.y, h, l); qh[r * PIT + c4 + 1] = h; ql[r * PIT + c4 + 1] = l;
        hilo(v.z, h, l); qh[r * PIT + c4 + 2] = h; ql[r * PIT + c4 + 2] = l;
        hilo(v.w, h, l); qh[r * PIT + c4 + 3] = h; ql[r * PIT + c4 + 3] = l;
    }

    float m_run[2] = { -1e30f, -1e30f };
    float l_run[2] = { 0.0f, 0.0f };
    float oacc[4][4];
#pragma unroll
    for (int i = 0; i < 4; i++)
#pragma unroll
        for (int j = 0; j < 4; j++) oacc[i][j] = 0.0f;

    const int ntiles = (qbase + BM) / BN;   // 2*qt + 2

    for (int kt = 0; kt < ntiles; kt++) {
        const int kbase = kt * BN;

        __syncthreads();   // prior tile's PV reads of vh/vl done
        for (int i = tid; i < BN * 16; i += 512) {
            const int r = i >> 4, c4 = (i & 15) << 2;
            float4 kv = *reinterpret_cast<const float4*>(&kp[(size_t)(kbase + r) * H_DIM + c4]);
            uint32_t h, l;
            hilo(kv.x, h, l); kh[r * PIT + c4 + 0] = h; kl[r * PIT + c4 + 0] = l;
            hilo(kv.y, h, l); kh[r * PIT + c4 + 1] = h; kl[r * PIT + c4 + 1] = l;
            hilo(kv.z, h, l); kh[r * PIT + c4 + 2] = h; kl[r * PIT + c4 + 2] = l;
            hilo(kv.w, h, l); kh[r * PIT + c4 + 3] = h; kl[r * PIT + c4 + 3] = l;
            float4 vv = *reinterpret_cast<const float4*>(&vp[(size_t)(kbase + r) * H_DIM + c4]);
            hilo(vv.x, h, l); vh[r * PIT + c4 + 0] = h; vl[r * PIT + c4 + 0] = l;
            hilo(vv.y, h, l); vh[r * PIT + c4 + 1] = h; vl[r * PIT + c4 + 1] = l;
            hilo(vv.z, h, l); vh[r * PIT + c4 + 2] = h; vl[r * PIT + c4 + 2] = l;
            hilo(vv.w, h, l); vh[r * PIT + c4 + 3] = h; vl[r * PIT + c4 + 3] = l;
        }
        if (tid < BN) msk[tid] = mask[(size_t)b * S_LEN + kbase + tid];
        __syncthreads();

        // ---- S = Q K^T (3xTF32): warp computes rows wr*16..+16, keys wc*32..+32
        float sacc[4][4];
#pragma unroll
        for (int i = 0; i < 4; i++)
#pragma unroll
            for (int j = 0; j < 4; j++) sacc[i][j] = 0.0f;

#pragma unroll
        for (int k8 = 0; k8 < 8; k8++) {
            const int kk = k8 * 8;
            const int ar = wr * 16 + g;
            uint32_t ah[4], al[4];
            ah[0] = qh[ar * PIT + kk + tq];     ah[1] = qh[(ar + 8) * PIT + kk + tq];
            ah[2] = qh[ar * PIT + kk + tq + 4]; ah[3] = qh[(ar + 8) * PIT + kk + tq + 4];
            al[0] = ql[ar * PIT + kk + tq];     al[1] = ql[(ar + 8) * PIT + kk + tq];
            al[2] = ql[ar * PIT + kk + tq + 4]; al[3] = ql[(ar + 8) * PIT + kk + tq + 4];
#pragma unroll
            for (int ni = 0; ni < 4; ni++) {
                const int kc = wc * 32 + ni * 8 + g;   // key index
                uint32_t bh[2] = { kh[kc * PIT + kk + tq], kh[kc * PIT + kk + tq + 4] };
                uint32_t bl[2] = { kl[kc * PIT + kk + tq], kl[kc * PIT + kk + tq + 4] };
                mma8(sacc[ni], ah, bh);
                mma8(sacc[ni], ah, bl);
                mma8(sacc[ni], al, bh);
            }
        }

        // ---- mask + per-row max (rows ri=0,1: wr*16 + ri*8 + g) ----
#pragma unroll
        for (int ri = 0; ri < 2; ri++) {
            const int row  = wr * 16 + ri * 8 + g;
            const int grow = qbase + row;
            float mx = -1e30f;
#pragma unroll
            for (int ni = 0; ni < 4; ni++)
#pragma unroll
                for (int c1 = 0; c1 < 2; c1++) {
                    const int kc = wc * 32 + ni * 8 + 2 * tq + c1;
                    const bool keep = ((kbase + kc) <= grow) && (msk[kc] != 0);
                    const float v = keep ? sacc[ni][ri * 2 + c1] * 0.125f : -1e30f;
                    sacc[ni][ri * 2 + c1] = v;
                    mx = fmaxf(mx, v);
                }
            mx = fmaxf(mx, __shfl_xor_sync(0xffffffffu, mx, 1));
            mx = fmaxf(mx, __shfl_xor_sync(0xffffffffu, mx, 2));
            if (tq == 0) redm[row][wc] = mx;
        }
        __syncthreads();

        float corr2[2];
#pragma unroll
        for (int ri = 0; ri < 2; ri++) {
            const int row = wr * 16 + ri * 8 + g;
            const float mt = fmaxf(redm[row][0], redm[row][1]);
            const float mn = fmaxf(m_run[ri], mt);
            corr2[ri] = __expf(m_run[ri] - mn);
            m_run[ri] = mn;

            float ls = 0.0f;
#pragma unroll
            for (int ni = 0; ni < 4; ni++)
#pragma unroll
                for (int c1 = 0; c1 < 2; c1++) {
                    const float v = sacc[ni][ri * 2 + c1];
                    const float p = (v > -1e29f) ? __expf(v - mn) : 0.0f;
                    const uint32_t pt = f2tf32(p);
                    ph[row * PIT + wc * 32 + ni * 8 + 2 * tq + c1] = pt;
                    ls += __uint_as_float(pt);   // sum the ROUNDED p (consistency)
                }
            ls += __shfl_xor_sync(0xffffffffu, ls, 1);
            ls += __shfl_xor_sync(0xffffffffu, ls, 2);
            if (tq == 0) reds[row][wc] = ls;
#pragma unroll
            for (int ni = 0; ni < 4; ni++)
#pragma unroll
                for (int c1 = 0; c1 < 2; c1++)
                    oacc[ni][ri * 2 + c1] *= corr2[ri];
        }
        __syncthreads();
#pragma unroll
        for (int ri = 0; ri < 2; ri++) {
            const int row = wr * 16 + ri * 8 + g;
            l_run[ri] = l_run[ri] * corr2[ri] + reds[row][0] + reds[row][1];
        }

        // ---- O += P V: warp rows wr*16..+16, h cols wc*32..+32 ----
#pragma unroll
        for (int k8 = 0; k8 < 8; k8++) {
            const int kk = k8 * 8;
            const int ar = wr * 16 + g;
            uint32_t ap[4];
            ap[0] = ph[ar * PIT + kk + tq];     ap[1] = ph[(ar + 8) * PIT + kk + tq];
            ap[2] = ph[ar * PIT + kk + tq + 4]; ap[3] = ph[(ar + 8) * PIT + kk + tq + 4];
#pragma unroll
            for (int ni = 0; ni < 4; ni++) {
                const int hc = wc * 32 + ni * 8 + g;
                uint32_t bh[2] = { vh[(kk + tq) * PIT + hc], vh[(kk + tq + 4) * PIT + hc] };
                uint32_t bl[2] = { vl[(kk + tq) * PIT + hc], vl[(kk + tq + 4) * PIT + hc] };
                mma8(oacc[ni], ap, bh);
                mma8(oacc[ni], ap, bl);
            }
        }
    }

    // ---- epilogue ----
#pragma unroll
    for (int ri = 0; ri < 2; ri++) {
        const int row = wr * 16 + ri * 8 + g;
        const float inv = 1.0f / l_run[ri];
#pragma unroll
        for (int ni = 0; ni < 4; ni++)
#pragma unroll
            for (int c1 = 0; c1 < 2; c1++) {
                const int col = wc * 32 + ni * 8 + 2 * tq + c1;
                out[((size_t)b * S_LEN + qbase + row) * H_DIM + col] =
                    oacc[ni][ri * 2 + c1] * inv;
            }
    }
}

// ---------------------------------------------------------------------------
extern "C" void kernel_launch(void* const* d_in, const int* in_sizes, int n_in,
                              void* d_out, int out_size)
{
    const float* x    = (const float*)d_in[0];
    const int*   mask = (const int*)  d_in[1];
    const float* Wq   = (const float*)d_in[2];
    const float* Wk   = (const float*)d_in[3];
    const float* Wv   = (const float*)d_in[4];
    float*       out  = (float*)d_out;

    const int proj_smem = (2 * 128 * PIT + 2 * 64 * PIT) * 4;   // 104448 B
    cudaFuncSetAttribute(proj_kernel, cudaFuncAttributeMaxDynamicSharedMemorySize,
                         proj_smem);
    dim3 pgrid((B_SZ * S_LEN) / 128, 3);
    proj_kernel<<<pgrid, 512, proj_smem>>>(x, Wq, Wk, Wv);

    const int attn_smem = (2 * 128 * PIT + 4 * 64 * PIT + 128 * PIT) * 4;  // 174080 B
    cudaFuncSetAttribute(attn_mma, cudaFuncAttributeMaxDynamicSharedMemorySize,
                         attn_smem);
    dim3 agrid(S_LEN / BM, B_SZ);   // 32 x 4
    attn_mma<<<agrid, 512, attn_smem>>>(mask, out);
}

// round 5
// speedup vs baseline: 10.0280x; 2.0027x over previous
#include <cuda_runtime.h>
#include <cuda_bf16.h>
#include <cstdint>
#include <cstddef>

#define S_LEN 4096
#define B_SZ  4
#define D_DIM 768
#define H_DIM 64

#define PB 72   // bf16 smem row pitch (stride 144B = 4 banks per row: ldmatrix conflict-free)
#define PW 36   // same pitch in u32

// bf16 hi/lo scratch (static device arrays: allocation-free). 2MB each.
__device__ unsigned short g_qh[B_SZ * S_LEN * H_DIM];
__device__ unsigned short g_ql[B_SZ * S_LEN * H_DIM];
__device__ unsigned short g_kh[B_SZ * S_LEN * H_DIM];
__device__ unsigned short g_kl[B_SZ * S_LEN * H_DIM];
__device__ unsigned short g_vth[B_SZ * H_DIM * S_LEN];   // V^T: [b][h][s]
__device__ unsigned short g_vtl[B_SZ * H_DIM * S_LEN];

// ===========================================================================
// helpers (sm_80+ PTX only)
// ===========================================================================
__device__ __forceinline__ uint32_t smem_u32(const void* p) {
    uint32_t a;
    asm("{ .reg .u64 t; cvta.to.shared.u64 t, %1; cvt.u32.u64 %0, t; }"
        : "=r"(a) : "l"(p));
    return a;
}

// pack bf16x2: lower = rn(lo), upper = rn(hi)
__device__ __forceinline__ uint32_t pack2(float lo, float hi) {
    uint32_t r;
    asm("cvt.rn.bf16x2.f32 %0, %2, %1;" : "=r"(r) : "f"(lo), "f"(hi));
    return r;
}

__device__ __forceinline__ float trunc_bf(float v) {
    return __uint_as_float(__float_as_uint(v) & 0xFFFF0000u);
}

__device__ __forceinline__ unsigned short bf16rn_u16(float v) {
    unsigned short r;
    asm("cvt.rn.bf16.f32 %0, %1;" : "=h"(r) : "f"(v));
    return r;
}

__device__ __forceinline__ void ldm_x4(uint32_t* r, uint32_t a) {
    asm volatile("ldmatrix.sync.aligned.m8n8.x4.shared.b16 {%0,%1,%2,%3}, [%4];"
                 : "=r"(r[0]), "=r"(r[1]), "=r"(r[2]), "=r"(r[3]) : "r"(a));
}
__device__ __forceinline__ void ldm_x2(uint32_t* r, uint32_t a) {
    asm volatile("ldmatrix.sync.aligned.m8n8.x2.shared.b16 {%0,%1}, [%2];"
                 : "=r"(r[0]), "=r"(r[1]) : "r"(a));
}

// D += A(16x16) * B(16x8), bf16 in, f32 accumulate.
__device__ __forceinline__ void mma16(float* c, const uint32_t* a, const uint32_t* b) {
    asm volatile(
        "mma.sync.aligned.m16n8k16.row.col.f32.bf16.bf16.f32 "
        "{%0,%1,%2,%3}, {%4,%5,%6,%7}, {%8,%9}, {%0,%1,%2,%3};"
        : "+f"(c[0]), "+f"(c[1]), "+f"(c[2]), "+f"(c[3])
        : "r"(a[0]), "r"(a[1]), "r"(a[2]), "r"(a[3]), "r"(b[0]), "r"(b[1]));
}

// Convert float4 (4 consecutive elems) to hi-pair/lo-pair u32s and store.
__device__ __forceinline__ void split_store4(uint32_t* hi, uint32_t* lo,
                                             int idx, float4 v) {
    hi[idx + 0] = __byte_perm(__float_as_uint(v.x), __float_as_uint(v.y), 0x7632);
    hi[idx + 1] = __byte_perm(__float_as_uint(v.z), __float_as_uint(v.w), 0x7632);
    lo[idx + 0] = pack2(v.x - trunc_bf(v.x), v.y - trunc_bf(v.y));
    lo[idx + 1] = pack2(v.z - trunc_bf(v.z), v.w - trunc_bf(v.w));
}

// ---------------------------------------------------------------------------
// Projection: out[row][h] = sum_d x[row][d] * W[h][d], 3-term bf16.
// 512 threads, 16 warps: wr = wid&7 (16 rows), wc = wid>>3 (32 cols).
// grid = (128, 3). Writes hi/lo bf16 (V transposed).
// ---------------------------------------------------------------------------
__global__ __launch_bounds__(512) void proj_kernel(
    const float* __restrict__ x,
    const float* __restrict__ Wq,
    const float* __restrict__ Wk,
    const float* __restrict__ Wv)
{
    extern __shared__ uint32_t psm[];
    uint32_t* xh = psm;              // [128][PW]
    uint32_t* xl = xh + 128 * PW;
    uint32_t* wh = xl + 128 * PW;    // [64][PW]
    uint32_t* wl = wh + 64 * PW;
    const uint32_t sb   = smem_u32(psm);
    const uint32_t xh_b = sb;
    const uint32_t xl_b = sb + 128 * PW * 4;
    const uint32_t wh_b = sb + 256 * PW * 4;
    const uint32_t wl_b = sb + (256 + 64) * PW * 4;

    const float* W = (blockIdx.y == 0) ? Wq : (blockIdx.y == 1) ? Wk : Wv;

    const int row0 = blockIdx.x * 128;
    const int tid  = threadIdx.x;
    const int wid  = tid >> 5, lane = tid & 31;
    const int wr   = wid & 7,  wc   = wid >> 3;
    const int g    = lane >> 2, tq  = lane & 3;
    const int seg  = lane >> 3, ii  = lane & 7;

    const uint32_t aoff = (uint32_t)((wr * 16 + ii + (seg & 1) * 8) * PB + (seg >> 1) * 8) * 2;
    const uint32_t boff = (uint32_t)((wc * 32 + ii) * PB + (seg & 1) * 8) * 2;

    float acc[4][4];
#pragma unroll
    for (int i = 0; i < 4; i++)
#pragma unroll
        for (int j = 0; j < 4; j++) acc[i][j] = 0.0f;

    for (int kc = 0; kc < 12; kc++) {
        const int k0 = kc * 64;
        __syncthreads();
        for (int i = tid; i < 128 * 16; i += 512) {
            const int r = i >> 4, c4 = (i & 15) << 2;
            float4 v = *reinterpret_cast<const float4*>(&x[(size_t)(row0 + r) * D_DIM + k0 + c4]);
            split_store4(xh, xl, r * PW + (c4 >> 1), v);
        }
        for (int i = tid; i < 64 * 16; i += 512) {
            const int r = i >> 4, c4 = (i & 15) << 2;
            float4 v = *reinterpret_cast<const float4*>(&W[(size_t)r * D_DIM + k0 + c4]);
            split_store4(wh, wl, r * PW + (c4 >> 1), v);
        }
        __syncthreads();

#pragma unroll
        for (int c4 = 0; c4 < 4; c4++) {
            uint32_t ah[4], al[4];
            ldm_x4(ah, xh_b + aoff + c4 * 32);
            ldm_x4(al, xl_b + aoff + c4 * 32);
#pragma unroll
            for (int ni = 0; ni < 4; ni++) {
                uint32_t bh[2], bl[2];
                ldm_x2(bh, wh_b + boff + ni * (8 * PB * 2) + c4 * 32);
                ldm_x2(bl, wl_b + boff + ni * (8 * PB * 2) + c4 * 32);
                mma16(acc[ni], ah, bh);
                mma16(acc[ni], ah, bl);
                mma16(acc[ni], al, bh);
            }
        }
    }

    // epilogue: hi/lo bf16 stores
#pragma unroll
    for (int ni = 0; ni < 4; ni++)
#pragma unroll
        for (int ri = 0; ri < 2; ri++)
#pragma unroll
            for (int c1 = 0; c1 < 2; c1++) {
                const int row = row0 + wr * 16 + ri * 8 + g;
                const int col = wc * 32 + ni * 8 + 2 * tq + c1;
                const float v  = acc[ni][ri * 2 + c1];
                const float hf = trunc_bf(v);
                const unsigned short h16 = (unsigned short)(__float_as_uint(v) >> 16);
                const unsigned short l16 = bf16rn_u16(v - hf);
                if (blockIdx.y == 0) {
                    g_qh[(size_t)row * H_DIM + col] = h16;
                    g_ql[(size_t)row * H_DIM + col] = l16;
                } else if (blockIdx.y == 1) {
                    g_kh[(size_t)row * H_DIM + col] = h16;
                    g_kl[(size_t)row * H_DIM + col] = l16;
                } else {
                    const int bb = row >> 12, s = row & 4095;
                    g_vth[((size_t)(bb * H_DIM + col)) * S_LEN + s] = h16;
                    g_vtl[((size_t)(bb * H_DIM + col)) * S_LEN + s] = l16;
                }
            }
}

// ---------------------------------------------------------------------------
// Flash attention, bf16 3-term mma.sync + ldmatrix.
// BM = BN = 64. 256 threads, 8 warps: wr = wid&3 (16 rows), wc = wid>>2 (32 cols).
// grid = (64, 4), longest tiles first. 2 CTAs/SM (72KB smem).
// ---------------------------------------------------------------------------
__global__ __launch_bounds__(256, 2) void attn_mma(
    const int* __restrict__ mask,
    float* __restrict__ out)
{
    extern __shared__ uint32_t asmem[];
    // carve: each tile = 64 rows x PW u32 = 2304 u32
    uint32_t* const tiles = asmem;
    const uint32_t sb   = smem_u32(asmem);
    const uint32_t qh_b = sb;
    const uint32_t ql_b = sb + 1 * 2304 * 4;
    const uint32_t kh_b = sb + 2 * 2304 * 4;
    const uint32_t kl_b = sb + 3 * 2304 * 4;
    const uint32_t vh_b = sb + 4 * 2304 * 4;
    const uint32_t vl_b = sb + 5 * 2304 * 4;
    const uint32_t ph_b = sb + 6 * 2304 * 4;
    uint32_t* const ph_u = tiles + 6 * 2304;
    uint32_t* const pl_u = tiles + 7 * 2304;
    const uint32_t pl_b = sb + 7 * 2304 * 4;

    __shared__ float redm[64][2];
    __shared__ float reds[64][2];
    __shared__ int   msk[64];

    const int tid  = threadIdx.x;
    const int wid  = tid >> 5, lane = tid & 31;
    const int wr   = wid & 3,  wc   = wid >> 2;
    const int g    = lane >> 2, tq  = lane & 3;
    const int seg  = lane >> 3, ii  = lane & 7;

    const int b     = blockIdx.y;
    const int qt    = 63 - blockIdx.x;        // longest first (LPT balance)
    const int qbase = qt * 64;

    const uint32_t aoff = (uint32_t)((wr * 16 + ii + (seg & 1) * 8) * PB + (seg >> 1) * 8) * 2;
    const uint32_t boff = (uint32_t)((wc * 32 + ii) * PB + (seg & 1) * 8) * 2;

    // ---- load Q tile (raw uint4 copies of precomputed bf16) ----
    {
        const uint4* sqh = reinterpret_cast<const uint4*>(g_qh) + ((size_t)b * S_LEN + qbase) * 8;
        const uint4* sql = reinterpret_cast<const uint4*>(g_ql) + ((size_t)b * S_LEN + qbase) * 8;
        uint4* dqh = reinterpret_cast<uint4*>(tiles + 0 * 2304);
        uint4* dql = reinterpret_cast<uint4*>(tiles + 1 * 2304);
        for (int i = tid; i < 512; i += 256) {
            const int r = i >> 3, c = i & 7;
            dqh[r * 9 + c] = sqh[r * 8 + c];
            dql[r * 9 + c] = sql[r * 8 + c];
        }
    }

    float m_run[2] = { -1e30f, -1e30f };
    float l_run[2] = { 0.0f, 0.0f };
    float oacc[4][4];
#pragma unroll
    for (int i = 0; i < 4; i++)
#pragma unroll
        for (int j = 0; j < 4; j++) oacc[i][j] = 0.0f;

    const int ntiles = qt + 1;

    for (int kt = 0; kt < ntiles; kt++) {
        const int kbase = kt * 64;

        __syncthreads();   // prior tile's MMA reads of k/v/p tiles done
        {
            const uint4* skh = reinterpret_cast<const uint4*>(g_kh) + ((size_t)b * S_LEN + kbase) * 8;
            const uint4* skl = reinterpret_cast<const uint4*>(g_kl) + ((size_t)b * S_LEN + kbase) * 8;
            const uint4* svh = reinterpret_cast<const uint4*>(g_vth) + ((size_t)b * H_DIM * S_LEN + kbase) / 8;
            const uint4* svl = reinterpret_cast<const uint4*>(g_vtl) + ((size_t)b * H_DIM * S_LEN + kbase) / 8;
            uint4* dkh = reinterpret_cast<uint4*>(tiles + 2 * 2304);
            uint4* dkl = reinterpret_cast<uint4*>(tiles + 3 * 2304);
            uint4* dvh = reinterpret_cast<uint4*>(tiles + 4 * 2304);
            uint4* dvl = reinterpret_cast<uint4*>(tiles + 5 * 2304);
            for (int i = tid; i < 512; i += 256) {
                const int r = i >> 3, c = i & 7;
                dkh[r * 9 + c] = skh[r * 8 + c];
                dkl[r * 9 + c] = skl[r * 8 + c];
                dvh[r * 9 + c] = svh[(size_t)r * 512 + c];   // row h: stride 4096 bf16 = 512 uint4
                dvl[r * 9 + c] = svl[(size_t)r * 512 + c];
            }
        }
        if (tid < 64) msk[tid] = mask[(size_t)b * S_LEN + kbase + tid];
        __syncthreads();

        // ---- S = Q K^T (3-term bf16) ----
        float sacc[4][4];
#pragma unroll
        for (int i = 0; i < 4; i++)
#pragma unroll
            for (int j = 0; j < 4; j++) sacc[i][j] = 0.0f;

#pragma unroll
        for (int c4 = 0; c4 < 4; c4++) {
            uint32_t ah[4], al[4];
            ldm_x4(ah, qh_b + aoff + c4 * 32);
            ldm_x4(al, ql_b + aoff + c4 * 32);
#pragma unroll
            for (int ni = 0; ni < 4; ni++) {
                uint32_t bh[2], bl[2];
                ldm_x2(bh, kh_b + boff + ni * (8 * PB * 2) + c4 * 32);
                ldm_x2(bl, kl_b + boff + ni * (8 * PB * 2) + c4 * 32);
                mma16(sacc[ni], ah, bh);
                mma16(sacc[ni], ah, bl);
                mma16(sacc[ni], al, bh);
            }
        }

        // ---- mask + row max ----
#pragma unroll
        for (int ri = 0; ri < 2; ri++) {
            const int row  = wr * 16 + ri * 8 + g;
            const int grow = qbase + row;
            float mx = -1e30f;
#pragma unroll
            for (int ni = 0; ni < 4; ni++)
#pragma unroll
                for (int c1 = 0; c1 < 2; c1++) {
                    const int kc = wc * 32 + ni * 8 + 2 * tq + c1;
                    const bool keep = ((kbase + kc) <= grow) && (msk[kc] != 0);
                    const float v = keep ? sacc[ni][ri * 2 + c1] * 0.125f : -1e30f;
                    sacc[ni][ri * 2 + c1] = v;
                    mx = fmaxf(mx, v);
                }
            mx = fmaxf(mx, __shfl_xor_sync(0xffffffffu, mx, 1));
            mx = fmaxf(mx, __shfl_xor_sync(0xffffffffu, mx, 2));
            if (tq == 0) redm[row][wc] = mx;
        }
        __syncthreads();

        float corr2[2];
#pragma unroll
        for (int ri = 0; ri < 2; ri++) {
            const int row = wr * 16 + ri * 8 + g;
            const float mt = fmaxf(redm[row][0], redm[row][1]);
            const float mn = fmaxf(m_run[ri], mt);
            corr2[ri] = __expf(m_run[ri] - mn);
            m_run[ri] = mn;

            float ls = 0.0f;
#pragma unroll
            for (int ni = 0; ni < 4; ni++) {
                const float v0 = sacc[ni][ri * 2 + 0];
                const float v1 = sacc[ni][ri * 2 + 1];
                const float p0 = (v0 > -1e29f) ? __expf(v0 - mn) : 0.0f;
                const float p1 = (v1 > -1e29f) ? __expf(v1 - mn) : 0.0f;
                const int pidx = row * PW + wc * 16 + ni * 4 + tq;
                ph_u[pidx] = __byte_perm(__float_as_uint(p0), __float_as_uint(p1), 0x7632);
                pl_u[pidx] = pack2(p0 - trunc_bf(p0), p1 - trunc_bf(p1));
                ls += p0 + p1;
            }
            ls += __shfl_xor_sync(0xffffffffu, ls, 1);
            ls += __shfl_xor_sync(0xffffffffu, ls, 2);
            if (tq == 0) reds[row][wc] = ls;
#pragma unroll
            for (int ni = 0; ni < 4; ni++)
#pragma unroll
                for (int c1 = 0; c1 < 2; c1++)
                    oacc[ni][ri * 2 + c1] *= corr2[ri];
        }
        __syncthreads();
#pragma unroll
        for (int ri = 0; ri < 2; ri++) {
            const int row = wr * 16 + ri * 8 + g;
            l_run[ri] = l_run[ri] * corr2[ri] + reds[row][0] + reds[row][1];
        }

        // ---- O += P V (3-term bf16) ----
#pragma unroll
        for (int c4 = 0; c4 < 4; c4++) {
            uint32_t ah[4], al[4];
            ldm_x4(ah, ph_b + aoff + c4 * 32);
            ldm_x4(al, pl_b + aoff + c4 * 32);
#pragma unroll
            for (int ni = 0; ni < 4; ni++) {
                uint32_t bh[2], bl[2];
                ldm_x2(bh, vh_b + boff + ni * (8 * PB * 2) + c4 * 32);
                ldm_x2(bl, vl_b + boff + ni * (8 * PB * 2) + c4 * 32);
                mma16(oacc[ni], ah, bh);
                mma16(oacc[ni], ah, bl);
                mma16(oacc[ni], al, bh);
            }
        }
    }

    // ---- epilogue ----
#pragma unroll
    for (int ri = 0; ri < 2; ri++) {
        const int row = wr * 16 + ri * 8 + g;
        const float inv = 1.0f / l_run[ri];
#pragma unroll
        for (int ni = 0; ni < 4; ni++) {
            const int col = wc * 32 + ni * 8 + 2 * tq;
            float2 w;
            w.x = oacc[ni][ri * 2 + 0] * inv;
            w.y = oacc[ni][ri * 2 + 1] * inv;
            *reinterpret_cast<float2*>(
                &out[((size_t)b * S_LEN + qbase + row) * H_DIM + col]) = w;
        }
    }
}

// ---------------------------------------------------------------------------
extern "C" void kernel_launch(void* const* d_in, const int* in_sizes, int n_in,
                              void* d_out, int out_size)
{
    const float* x    = (const float*)d_in[0];
    const int*   mask = (const int*)  d_in[1];
    const float* Wq   = (const float*)d_in[2];
    const float* Wk   = (const float*)d_in[3];
    const float* Wv   = (const float*)d_in[4];
    float*       out  = (float*)d_out;

    const int proj_smem = (2 * 128 * PW + 2 * 64 * PW) * 4;   // 55296 B
    cudaFuncSetAttribute(proj_kernel, cudaFuncAttributeMaxDynamicSharedMemorySize,
                         proj_smem);
    dim3 pgrid((B_SZ * S_LEN) / 128, 3);
    proj_kernel<<<pgrid, 512, proj_smem>>>(x, Wq, Wk, Wv);

    const int attn_smem = 8 * 2304 * 4;   // 73728 B -> 2 CTAs/SM
    cudaFuncSetAttribute(attn_mma, cudaFuncAttributeMaxDynamicSharedMemorySize,
                         attn_smem);
    dim3 agrid(64, B_SZ);   // 256 CTAs
    attn_mma<<<agrid, 256, attn_smem>>>(mask, out);
}